// round 3
// baseline (speedup 1.0000x reference)
#include <cuda_runtime.h>
#include <cuda_bf16.h>

// CSR multi-head SpMM: out[n,h,d] = sum_{e in row n} ew[e,h] * nf[col[e],h,d]
// N=50000, E=800000, H=8, D=8 -> 64 floats per row.
//
// One warp per destination row. Lane L owns output elements 2L, 2L+1 (float2),
// head h = L>>2.
//
// R2: batch-load 32 col indices per warp with ONE coalesced LDG, broadcast via
// __shfl_sync. This removes the col->feat dependent-load chain from the inner
// loop: all (up to) 32 node_feat gathers in a batch are independent -> MLP ~32
// instead of ~4. Weight loads are address-independent and overlap freely.

#define H 8
#define D 8
#define ROW_ELEMS (H * D)

__global__ __launch_bounds__(256) void spmm_csr_kernel(
    const int* __restrict__ row_ptr,
    const int* __restrict__ col_idx,
    const float* __restrict__ edge_weight,   // [E, 8]
    const float* __restrict__ node_feat,     // [N, 64]
    float* __restrict__ out,                 // [N, 64]
    int n_nodes)
{
    int warp = (blockIdx.x * blockDim.x + threadIdx.x) >> 5;
    int lane = threadIdx.x & 31;
    if (warp >= n_nodes) return;

    int start = __ldg(&row_ptr[warp]);
    int end   = __ldg(&row_ptr[warp + 1]);

    int h = lane >> 2;                 // head index for this lane's float2
    float accx = 0.0f, accy = 0.0f;

    for (int base = start; base < end; base += 32) {
        int e = base + lane;
        // one coalesced load of up to 32 column indices for this warp
        int c = (e < end) ? __ldg(&col_idx[e]) : 0;
        int nb = min(32, end - base);  // uniform across the warp

        #pragma unroll
        for (int j = 0; j < 32; ++j) {
            if (j >= nb) break;        // uniform exit, no divergence
            int cj  = __shfl_sync(0xffffffffu, c, j);
            float w = __ldg(&edge_weight[(size_t)(base + j) * H + h]);
            float2 f = *reinterpret_cast<const float2*>(
                node_feat + (size_t)cj * ROW_ELEMS + lane * 2);
            accx = fmaf(w, f.x, accx);
            accy = fmaf(w, f.y, accy);
        }
    }

    float2 r; r.x = accx; r.y = accy;
    *reinterpret_cast<float2*>(out + (size_t)warp * ROW_ELEMS + lane * 2) = r;
}

extern "C" void kernel_launch(void* const* d_in, const int* in_sizes, int n_in,
                              void* d_out, int out_size)
{
    const int*   row_ptr     = (const int*)d_in[0];
    const int*   col_idx     = (const int*)d_in[1];
    const float* edge_weight = (const float*)d_in[2];
    const float* node_feat   = (const float*)d_in[3];
    float*       out         = (float*)d_out;

    int n_nodes = in_sizes[0] - 1;          // row_ptr has N+1 entries

    const int threads = 256;                 // 8 warps / block
    int blocks = (n_nodes * 32 + threads - 1) / threads;
    spmm_csr_kernel<<<blocks, threads>>>(row_ptr, col_idx, edge_weight,
                                         node_feat, out, n_nodes);
}

// round 4
// speedup vs baseline: 1.5482x; 1.5482x over previous
#include <cuda_runtime.h>
#include <cuda_bf16.h>

// CSR multi-head SpMM: out[n,h,d] = sum_{e in row n} ew[e,h] * nf[col[e],h,d]
// N=50000, E=800000, H=8, D=8 -> 64 floats per row.
//
// One warp per destination row. Lane L owns output elements 2L, 2L+1 (float2),
// head h = L>>2. Gather of a node_feat row = one coalesced 256B warp read
// (node_feat is 12.8MB -> resident in L2 after warm-up).
//
// R3: back to the R1 structure (which compiled to front-batched loads) but
// unroll 8 with a relaxed register budget (launch_bounds 256,4 -> 64 regs),
// so ptxas batches 8 independent col LDGs + 8 weight LDGs + 8 feat LDGs per
// iteration. Halves the number of exposed col->feat L2 round-trips per row.

#define H 8
#define D 8
#define ROW_ELEMS (H * D)

__global__ __launch_bounds__(256, 4) void spmm_csr_kernel(
    const int* __restrict__ row_ptr,
    const int* __restrict__ col_idx,
    const float* __restrict__ edge_weight,   // [E, 8]
    const float* __restrict__ node_feat,     // [N, 64]
    float* __restrict__ out,                 // [N, 64]
    int n_nodes)
{
    int warp = (blockIdx.x * blockDim.x + threadIdx.x) >> 5;
    int lane = threadIdx.x & 31;
    if (warp >= n_nodes) return;

    int start = __ldg(&row_ptr[warp]);
    int end   = __ldg(&row_ptr[warp + 1]);

    int h = lane >> 2;                 // head index for this lane's float2
    float accx = 0.0f, accy = 0.0f;

    #pragma unroll 8
    for (int e = start; e < end; ++e) {
        int c   = __ldg(&col_idx[e]);
        float w = __ldg(&edge_weight[(size_t)e * H + h]);
        float2 f = *reinterpret_cast<const float2*>(
            node_feat + (size_t)c * ROW_ELEMS + lane * 2);
        accx = fmaf(w, f.x, accx);
        accy = fmaf(w, f.y, accy);
    }

    float2 r; r.x = accx; r.y = accy;
    *reinterpret_cast<float2*>(out + (size_t)warp * ROW_ELEMS + lane * 2) = r;
}

extern "C" void kernel_launch(void* const* d_in, const int* in_sizes, int n_in,
                              void* d_out, int out_size)
{
    const int*   row_ptr     = (const int*)d_in[0];
    const int*   col_idx     = (const int*)d_in[1];
    const float* edge_weight = (const float*)d_in[2];
    const float* node_feat   = (const float*)d_in[3];
    float*       out         = (float*)d_out;

    int n_nodes = in_sizes[0] - 1;          // row_ptr has N+1 entries

    const int threads = 256;                 // 8 warps / block
    int blocks = (n_nodes * 32 + threads - 1) / threads;
    spmm_csr_kernel<<<blocks, threads>>>(row_ptr, col_idx, edge_weight,
                                         node_feat, out, n_nodes);
}